// round 6
// baseline (speedup 1.0000x reference)
#include <cuda_runtime.h>
#include <math.h>
#include <stdint.h>

#define NPOS 2500
#define NPAD 2560
#define NANCH 22500
#define PRE 6000
#define POST 300
#define CAP 8192
#define KSPLIT 12
#define KPART 384          // 4608 / 12
#define LW 188             // 6000 bits -> 188 u32 words

typedef unsigned long long ull;

// ---------------- scratch ----------------
__device__ float g_wt[4608 * 512];              // transposed weights [K][M]
__device__ float g_col[4608 * NPAD];            // im2col matrix [4608][2560]
__device__ float g_part[KSPLIT][512 * NPAD];    // split-K partials
__device__ float4 g_boxes[NANCH];
__device__ unsigned int g_key32[NANCH];
__device__ unsigned int g_hist[65536];

// ---------------- f32x2 helpers ----------------
__device__ __forceinline__ void fma2(ull& d, ull a, ull b) {
    asm("fma.rn.f32x2 %0, %1, %2, %0;" : "+l"(d) : "l"(a), "l"(b));
}
__device__ __forceinline__ ull splat2(float x) {
    ull r;
    unsigned u = __float_as_uint(x);
    asm("mov.b64 %0, {%1, %1};" : "=l"(r) : "r"(u));
    return r;
}

// ---------------- weight transpose (+ hist zero folded in) ----------------
__global__ __launch_bounds__(256) void wt_kernel(const float* __restrict__ W) {
    __shared__ float sm[32][33];
    int k0 = blockIdx.x * 32;
    int m0 = blockIdx.y * 32;
    int tx = threadIdx.x & 31;
    int ty = threadIdx.x >> 5;     // 0..7
    if (blockIdx.y == 0 && blockIdx.x < 256)
        g_hist[blockIdx.x * 256 + threadIdx.x] = 0u;
#pragma unroll
    for (int i = 0; i < 4; i++)
        sm[ty + i * 8][tx] = W[(size_t)(m0 + ty + i * 8) * 4608 + k0 + tx];
    __syncthreads();
#pragma unroll
    for (int i = 0; i < 4; i++)
        g_wt[(size_t)(k0 + ty + i * 8) * 512 + m0 + tx] = sm[tx][ty + i * 8];
}

// ---------------- im2col: g_col[k][n] ----------------
__global__ __launch_bounds__(256) void im2col_kernel(const float* __restrict__ in) {
    int n = blockIdx.x * 256 + threadIdx.x;     // 0..2559
    int k = blockIdx.y;                          // 0..4607
    if (n >= NPAD) return;
    float v = 0.f;
    if (n < NPOS) {
        int ci = k / 9;
        int r = k - ci * 9;
        int kh = r / 3;
        int kw = r - kh * 3;
        int h = n / 50;
        int w = n - h * 50;
        int ih = h + kh - 1;
        int iw = w + kw - 1;
        if (ih >= 0 && ih < 50 && iw >= 0 && iw < 50)
            v = in[ci * NPOS + ih * 50 + iw];
    }
    g_col[(size_t)k * NPAD + n] = v;
}

// ---------------- conv GEMM: split-K, 128x64 tiles, 128 thr, pre-splatted A ----------------
__global__ __launch_bounds__(128, 4) void conv_gemm_kernel() {
    __shared__ ull As[2][16][128];     // pre-splatted f32x2 weights
    __shared__ float Bs[2][16][64];
    const int bn = blockIdx.x * 64;
    const int bm = blockIdx.y * 128;
    const int kb = blockIdx.z * KPART;
    const int t = threadIdx.x;
    const int tm = t >> 3;    // 0..15
    const int tn = t & 7;     // 0..7

    ull acc[8][4];
#pragma unroll
    for (int i = 0; i < 8; i++)
#pragma unroll
        for (int j = 0; j < 4; j++) acc[i][j] = 0ull;

    int akl[4], amc[4];
#pragma unroll
    for (int p = 0; p < 4; p++) {
        int q = t + 128 * p;
        akl[p] = q >> 5;
        amc[p] = (q & 31) * 4;
    }
    int bkl[2], bnc[2];
#pragma unroll
    for (int p = 0; p < 2; p++) {
        int q = t + 128 * p;
        bkl[p] = q >> 4;
        bnc[p] = (q & 15) * 4;
    }

    float4 ar[4], br[2];
#pragma unroll
    for (int p = 0; p < 4; p++)
        ar[p] = *(const float4*)&g_wt[(size_t)(kb + akl[p]) * 512 + bm + amc[p]];
#pragma unroll
    for (int p = 0; p < 2; p++)
        br[p] = *(const float4*)&g_col[(size_t)(kb + bkl[p]) * NPAD + bn + bnc[p]];
#pragma unroll
    for (int p = 0; p < 4; p++) {
        As[0][akl[p]][amc[p] + 0] = splat2(ar[p].x);
        As[0][akl[p]][amc[p] + 1] = splat2(ar[p].y);
        As[0][akl[p]][amc[p] + 2] = splat2(ar[p].z);
        As[0][akl[p]][amc[p] + 3] = splat2(ar[p].w);
    }
#pragma unroll
    for (int p = 0; p < 2; p++)
        *(float4*)&Bs[0][bkl[p]][bnc[p]] = br[p];
    __syncthreads();

    int cur = 0;
    for (int it = 0; it < KPART / 16; it++) {
        int nxt = cur ^ 1;
        bool more = (it + 1) < KPART / 16;
        if (more) {
            int k0 = kb + (it + 1) * 16;
#pragma unroll
            for (int p = 0; p < 4; p++)
                ar[p] = *(const float4*)&g_wt[(size_t)(k0 + akl[p]) * 512 + bm + amc[p]];
#pragma unroll
            for (int p = 0; p < 2; p++)
                br[p] = *(const float4*)&g_col[(size_t)(k0 + bkl[p]) * NPAD + bn + bnc[p]];
        }
#pragma unroll
        for (int kk = 0; kk < 16; kk++) {
            ulonglong2 a01 = *(const ulonglong2*)&As[cur][kk][tm * 8];
            ulonglong2 a23 = *(const ulonglong2*)&As[cur][kk][tm * 8 + 2];
            ulonglong2 a45 = *(const ulonglong2*)&As[cur][kk][tm * 8 + 4];
            ulonglong2 a67 = *(const ulonglong2*)&As[cur][kk][tm * 8 + 6];
            ull bb0 = *(const ull*)&Bs[cur][kk][tn * 8];
            ull bb1 = *(const ull*)&Bs[cur][kk][tn * 8 + 2];
            ull bb2 = *(const ull*)&Bs[cur][kk][tn * 8 + 4];
            ull bb3 = *(const ull*)&Bs[cur][kk][tn * 8 + 6];
            ull aa[8] = {a01.x, a01.y, a23.x, a23.y, a45.x, a45.y, a67.x, a67.y};
#pragma unroll
            for (int i = 0; i < 8; i++) {
                fma2(acc[i][0], aa[i], bb0);
                fma2(acc[i][1], aa[i], bb1);
                fma2(acc[i][2], aa[i], bb2);
                fma2(acc[i][3], aa[i], bb3);
            }
        }
        if (more) {
#pragma unroll
            for (int p = 0; p < 4; p++) {
                As[nxt][akl[p]][amc[p] + 0] = splat2(ar[p].x);
                As[nxt][akl[p]][amc[p] + 1] = splat2(ar[p].y);
                As[nxt][akl[p]][amc[p] + 2] = splat2(ar[p].z);
                As[nxt][akl[p]][amc[p] + 3] = splat2(ar[p].w);
            }
#pragma unroll
            for (int p = 0; p < 2; p++)
                *(float4*)&Bs[nxt][bkl[p]][bnc[p]] = br[p];
        }
        __syncthreads();
        cur = nxt;
    }

    float* dst = &g_part[blockIdx.z][(size_t)(bm + tm * 8) * NPAD + bn + tn * 8];
#pragma unroll
    for (int i = 0; i < 8; i++) {
        *(ull*)&dst[(size_t)i * NPAD]     = acc[i][0];
        *(ull*)&dst[(size_t)i * NPAD + 2] = acc[i][1];
        *(ull*)&dst[(size_t)i * NPAD + 4] = acc[i][2];
        *(ull*)&dst[(size_t)i * NPAD + 6] = acc[i][3];
    }
}

// ---------------- head GEMM + fused split-K reduce + bias + leaky + decode ----------------
__global__ __launch_bounds__(256) void head_decode_kernel(const float* __restrict__ reg_w,
                                                          const float* __restrict__ cls_w,
                                                          const float* __restrict__ conv_b,
                                                          const float* __restrict__ reg_b,
                                                          const float* __restrict__ cls_b) {
    __shared__ float As[16][64];
    __shared__ float Bs[16][64];
    __shared__ float Psm[54][65];
    const int bn = blockIdx.x * 64;
    const int t = threadIdx.x;
    float acc[4][4];
#pragma unroll
    for (int i = 0; i < 4; i++)
#pragma unroll
        for (int j = 0; j < 4; j++) acc[i][j] = 0.f;

    const int tm = t >> 4, tn = t & 15;

    for (int k0 = 0; k0 < 512; k0 += 16) {
        {
            int m = t >> 2;
            int kq = (t & 3) * 4;
            float4 v = make_float4(0.f, 0.f, 0.f, 0.f);
            if (m < 36) v = *(const float4*)&reg_w[m * 512 + k0 + kq];
            else if (m < 54) v = *(const float4*)&cls_w[(m - 36) * 512 + k0 + kq];
            As[kq + 0][m] = v.x;
            As[kq + 1][m] = v.y;
            As[kq + 2][m] = v.z;
            As[kq + 3][m] = v.w;
        }
        {
            int kl = t >> 4;
            int nq = (t & 15) * 4;
            size_t off = (size_t)(k0 + kl) * NPAD + bn + nq;
            float4 v = *(const float4*)&g_part[0][off];
#pragma unroll
            for (int s2 = 1; s2 < KSPLIT; s2++) {
                float4 p = *(const float4*)&g_part[s2][off];
                v.x += p.x; v.y += p.y; v.z += p.z; v.w += p.w;
            }
            float bv = conv_b[k0 + kl];
            v.x += bv; v.y += bv; v.z += bv; v.w += bv;
            v.x = (v.x >= 0.f) ? v.x : 0.01f * v.x;
            v.y = (v.y >= 0.f) ? v.y : 0.01f * v.y;
            v.z = (v.z >= 0.f) ? v.z : 0.01f * v.z;
            v.w = (v.w >= 0.f) ? v.w : 0.01f * v.w;
            *(float4*)&Bs[kl][nq] = v;
        }
        __syncthreads();
#pragma unroll
        for (int kk = 0; kk < 16; kk++) {
            float a[4], b[4];
            *(float4*)&a[0] = *(float4*)&As[kk][tm * 4];
            *(float4*)&b[0] = *(float4*)&Bs[kk][tn * 4];
#pragma unroll
            for (int i = 0; i < 4; i++)
#pragma unroll
                for (int j = 0; j < 4; j++) acc[i][j] += a[i] * b[j];
        }
        __syncthreads();
    }
#pragma unroll
    for (int i = 0; i < 4; i++) {
        int m = tm * 4 + i;
        if (m < 54)
#pragma unroll
            for (int j = 0; j < 4; j++) Psm[m][tn * 4 + j] = acc[i][j];
    }
    __syncthreads();

    for (int c = t; c < 576; c += 256) {
        int pl = c / 9;
        int a = c - pl * 9;
        int pos = bn + pl;
        if (pos >= NPOS) continue;
        int h = pos / 50;
        int w = pos - h * 50;

        float pr0 = Psm[4 * a + 0][pl] + reg_b[4 * a + 0];
        float pr1 = Psm[4 * a + 1][pl] + reg_b[4 * a + 1];
        float pr2 = Psm[4 * a + 2][pl] + reg_b[4 * a + 2];
        float pr3 = Psm[4 * a + 3][pl] + reg_b[4 * a + 3];
        float l0 = Psm[36 + 2 * a + 0][pl] + cls_b[2 * a + 0];
        float l1 = Psm[36 + 2 * a + 1][pl] + cls_b[2 * a + 1];

        float mx = fmaxf(l0, l1);
        float e0 = expf(l0 - mx);
        float e1 = expf(l1 - mx);
        float score = e1 / (e0 + e1);

        const float rs_[3] = {0.5f, 1.0f, 2.0f};
        const float ss_[3] = {8.0f, 16.0f, 32.0f};
        int ri = a / 3;
        int si = a - ri * 3;
        float hs = (16.0f * ss_[si]) * sqrtf(rs_[ri]);
        float ws = (16.0f * ss_[si]) * sqrtf(1.0f / rs_[ri]);
        float cx = 16.0f * (float)h + 8.0f;
        float cy = 16.0f * (float)w + 8.0f;
        float ax1 = cx - ws * 0.5f;
        float ay1 = cy - hs * 0.5f;

        const float hi = 799.0f;
        float rx1 = fminf(fmaxf(pr0 + ax1, 0.f), hi);
        float ry1 = fminf(fmaxf(pr1 + ay1, 0.f), hi);
        float rx2 = fminf(fmaxf(pr0 + ax1 + pr2 + ws, 0.f), hi);
        float ry2 = fminf(fmaxf(pr1 + ay1 + pr3 + hs, 0.f), hi);

        float wv = pr2 + ws;
        float hv = pr3 + hs;
        bool valid = (wv >= 16.0f) && (hv >= 16.0f);
        float s = valid ? score : -INFINITY;

        int idx = pos * 9 + a;
        g_boxes[idx] = make_float4(rx1, ry1, rx2, ry2);

        unsigned u = __float_as_uint(s);
        u = (u & 0x80000000u) ? ~u : (u | 0x80000000u);
        unsigned du = ~u;
        g_key32[idx] = du;
        atomicAdd(&g_hist[du >> 16], 1u);
    }
}

// ---------------- tail: select + compact + sort + NMS + output (one block) ----------------
extern __shared__ char tsm[];
__global__ __launch_bounds__(1024) void tail_kernel(float* __restrict__ out) {
    ull* s = (ull*)tsm;                              // CAP * 8 = 64KB
    float* X1 = (float*)(tsm + CAP * 8);             // 5 * PRE * 4 = 120KB
    float* Y1 = X1 + PRE;
    float* X2 = Y1 + PRE;
    float* Y2 = X2 + PRE;
    float* AR = Y2 + PRE;
    int* sel = (int*)(AR + PRE);                     // POST ints
    __shared__ unsigned ps[1024];
    __shared__ unsigned live[LW];
    __shared__ unsigned kf[LW];
    __shared__ unsigned s_cut, s_cnt;
    __shared__ int s_cur, s_nsel, s_wpos;
    const int t = threadIdx.x;
    const int lane = t & 31;
    const int wid = t >> 5;

    // ---- phase 1: histogram cutoff + prefill sort keys ----
    {
        unsigned sum = 0;
        int base = t * 64;
#pragma unroll 8
        for (int b = 0; b < 64; b++) sum += g_hist[base + b];
        ps[t] = sum;
        __syncthreads();
        for (int off = 1; off < 1024; off <<= 1) {
            unsigned v = (t >= off) ? ps[t - off] : 0u;
            __syncthreads();
            ps[t] += v;
            __syncthreads();
        }
        unsigned excl = ps[t] - sum;
        if (excl < PRE && ps[t] >= PRE) {
            unsigned c = excl;
            for (int b = 0; b < 64; b++) {
                c += g_hist[base + b];
                if (c >= PRE) { s_cut = (unsigned)(base + b); break; }
            }
        }
        if (t == 0) s_cnt = 0u;
        for (int i = t; i < CAP; i += 1024) s[i] = 0xFFFFFFFFFFFFFFFFull;
    }
    __syncthreads();

    // ---- phase 2: compact candidates <= cutoff ----
    {
        unsigned cut = s_cut;
        for (int i = t; i < NANCH; i += 1024) {
            unsigned k = g_key32[i];
            if ((k >> 16) <= cut) {
                unsigned p = atomicAdd(&s_cnt, 1u);
                if (p < CAP) s[p] = ((ull)k << 32) | (unsigned)i;
            }
        }
    }
    __syncthreads();

    // ---- phase 3: bitonic sort (ascending, 8192) ----
    for (int k = 2; k <= CAP; k <<= 1) {
        for (int j = k >> 1; j > 0; j >>= 1) {
#pragma unroll
            for (int p = 0; p < 4; p++) {
                int q = t + p * 1024;
                int i = ((q & ~(j - 1)) << 1) | (q & (j - 1));
                int pp = i | j;
                bool up = ((i & k) == 0);
                ull a = s[i], b = s[pp];
                bool sw = up ? (a > b) : (a < b);
                if (sw) { s[i] = b; s[pp] = a; }
            }
            __syncthreads();
        }
    }

    // ---- phase 4: gather top-6000 boxes ----
    for (int r = t; r < PRE; r += 1024) {
        int idx = (int)(s[r] & 0xFFFFFFFFull);
        float4 b = g_boxes[idx];
        X1[r] = b.x; Y1[r] = b.y; X2[r] = b.z; Y2[r] = b.w;
        AR[r] = (b.z - b.x + 1.0f) * (b.w - b.y + 1.0f);
    }
    if (t < LW) {
        live[t] = (t == LW - 1) ? 0x0000FFFFu : 0xFFFFFFFFu;  // 187*32+16 = 6000
        kf[t] = 0u;
    }
    if (t == 0) { s_nsel = 0; s_wpos = 0; }
    __syncthreads();

    // ---- phase 5: greedy NMS with live-word skipping ----
    while (true) {
        if (t == 0) {
            if (s_nsel >= POST) {
                s_cur = -1;
            } else {
                int w = s_wpos;
                unsigned word = 0;
                while (w < LW && (word = live[w]) == 0u) w++;
                s_wpos = w;
                if (w == LW) {
                    s_cur = -1;
                } else {
                    int b = __ffs(word) - 1;
                    int cur = w * 32 + b;
                    live[w] = word & ~(1u << b);
                    kf[w] |= 1u << b;
                    sel[s_nsel++] = cur;
                    s_cur = cur;
                }
            }
        }
        __syncthreads();
        int cur = s_cur;
        if (cur < 0) break;

        float x1i = X1[cur], y1i = Y1[cur], x2i = X2[cur], y2i = Y2[cur], ai = AR[cur];
        int w0 = (cur + 1) >> 5;
        int off = (cur + 1) & 31;
        for (int w = w0 + wid; w < LW; w += 32) {
            unsigned wv = live[w];
            if (w == w0) wv &= 0xFFFFFFFFu << off;
            if (wv == 0u) continue;
            bool supp = false;
            if ((wv >> lane) & 1u) {
                int j = w * 32 + lane;
                float xx1 = fmaxf(x1i, X1[j]);
                float yy1 = fmaxf(y1i, Y1[j]);
                float xx2 = fminf(x2i, X2[j]);
                float yy2 = fmaxf(y2i, Y2[j]);   // reference's maximum bug preserved
                float ww = fmaxf(0.f, xx2 - xx1 + 1.0f);
                float hh = fmaxf(0.f, yy2 - yy1 + 1.0f);
                float inter = ww * hh;
                float ov = inter / (ai + AR[j] - inter);
                supp = (ov > 0.7f);
            }
            unsigned m = __ballot_sync(0xFFFFFFFFu, supp);
            if (lane == 0 && m) atomicAnd(&live[w], ~m);
        }
        __syncthreads();
    }

    // pad with suppressed (ascending rank): suppressed = ~live & ~kf (valid bits only)
    if (t == 0 && s_nsel < POST) {
        int c = s_nsel;
        for (int w = 0; w < LW && c < POST; w++) {
            unsigned valid = (w == LW - 1) ? 0x0000FFFFu : 0xFFFFFFFFu;
            unsigned word = ~live[w] & ~kf[w] & valid;
            while (word && c < POST) {
                int b = __ffs(word) - 1;
                sel[c++] = w * 32 + b;
                word &= word - 1;
            }
        }
        s_nsel = c;
    }
    __syncthreads();

    // ---- phase 6: output ----
    if (t < POST) {
        int rk = sel[t];
        out[t * 4 + 0] = X1[rk];
        out[t * 4 + 1] = Y1[rk];
        out[t * 4 + 2] = X2[rk] - X1[rk] + 1.0f;
        out[t * 4 + 3] = Y2[rk] - Y1[rk] + 1.0f;
    }
}

// ---------------- launch ----------------
extern "C" void kernel_launch(void* const* d_in, const int* in_sizes, int n_in,
                              void* d_out, int out_size) {
    const float* in_features = (const float*)d_in[0];
    const float* conv_w = (const float*)d_in[1];
    const float* conv_b = (const float*)d_in[2];
    const float* reg_w = (const float*)d_in[3];
    const float* reg_b = (const float*)d_in[4];
    const float* cls_w = (const float*)d_in[5];
    const float* cls_b = (const float*)d_in[6];
    float* out = (float*)d_out;

    const float* in7 = in_features + (size_t)7 * 512 * NPOS;  // only batch -1 consumed

    wt_kernel<<<dim3(144, 16), 256>>>(conv_w);
    im2col_kernel<<<dim3(10, 4608), 256>>>(in7);
    conv_gemm_kernel<<<dim3(40, 4, KSPLIT), 128>>>();
    head_decode_kernel<<<40, 256>>>(reg_w, cls_w, conv_b, reg_b, cls_b);

    const int tail_smem = CAP * 8 + 5 * PRE * 4 + POST * 4 + 64;
    cudaFuncSetAttribute(tail_kernel, cudaFuncAttributeMaxDynamicSharedMemorySize, tail_smem);
    tail_kernel<<<1, 1024, tail_smem>>>(out);
}